// round 1
// baseline (speedup 1.0000x reference)
#include <cuda_runtime.h>
#include <stdint.h>

#define HH 512
#define WW 512
#define NB 4

// Packed border tensor: 16 channels x 2 bits per pixel (values in {0,1,2}).
__device__ uint32_t g_border[NB * HH * WW];

// ---------------------------------------------------------------------------
// Stage 1: 11x11 conv (1->8 ch) on both input planes + spike/WTA logic.
// Block (32,16), tile 32x32 (each thread owns rows ty and ty+16).
// ---------------------------------------------------------------------------
__global__ __launch_bounds__(512)
void stage1_kernel(const float* __restrict__ inp, const float* __restrict__ Wb)
{
    __shared__ float sh0[42][44];
    __shared__ float sh1[42][44];
    __shared__ float wsh[968];

    const int b  = blockIdx.z;
    const int x0 = blockIdx.x * 32;
    const int y0 = blockIdx.y * 32;
    const int tx = threadIdx.x;      // 0..31
    const int ty = threadIdx.y;      // 0..15
    const int tid = ty * 32 + tx;

    for (int i = tid; i < 968; i += 512) wsh[i] = Wb[i];

    const float* __restrict__ in0 = inp + ((size_t)b * 2 + 0) * HH * WW;
    const float* __restrict__ in1 = inp + ((size_t)b * 2 + 1) * HH * WW;

    for (int i = tid; i < 42 * 42; i += 512) {
        int ry = i / 42, rx = i - ry * 42;
        int gy = y0 - 5 + ry, gx = x0 - 5 + rx;
        bool ok = ((unsigned)gy < HH) && ((unsigned)gx < WW);
        sh0[ry][rx] = ok ? in0[gy * WW + gx] : 0.0f;
        sh1[ry][rx] = ok ? in1[gy * WW + gx] : 0.0f;
    }
    __syncthreads();

    float ap[2][8], an[2][8];
    #pragma unroll
    for (int f = 0; f < 8; ++f) {
        ap[0][f] = 0.f; an[0][f] = 0.f; ap[1][f] = 0.f; an[1][f] = 0.f;
    }

    for (int dy = 0; dy < 11; ++dy) {
        #pragma unroll
        for (int dx = 0; dx < 11; ++dx) {
            float x00 = sh0[ty + dy][tx + dx];
            float x10 = sh1[ty + dy][tx + dx];
            float x01 = sh0[ty + 16 + dy][tx + dx];
            float x11 = sh1[ty + 16 + dy][tx + dx];
            const int t = dy * 11 + dx;
            #pragma unroll
            for (int f = 0; f < 8; ++f) {
                float w = wsh[f * 121 + t];
                ap[0][f] += w * x00;
                an[0][f] += w * x10;
                ap[1][f] += w * x01;
                an[1][f] += w * x11;
            }
        }
    }

    #pragma unroll
    for (int k = 0; k < 2; ++k) {
        const int yy = ty + k * 16;
        float vm = sh0[yy + 5][tx + 5] + sh1[yy + 5][tx + 5];

        int b13[4], b24[4];
        #pragma unroll
        for (int o = 0; o < 4; ++o) {
            float pe = ap[k][2*o]   >= 1.0f ? 1.0f : 0.0f;
            float po = ap[k][2*o+1] >= 1.0f ? 1.0f : 0.0f;
            float ne = an[k][2*o]   >= 1.0f ? 1.0f : 0.0f;
            float no = an[k][2*o+1] >= 1.0f ? 1.0f : 0.0f;
            int s1 = (vm * (pe - 1.5f * no) >= 1.0f) ? 1 : 0;
            int s2 = (vm * (ne - 1.5f * po) >= 1.0f) ? 1 : 0;
            int s3 = (vm * (po - 1.5f * ne) >= 1.0f) ? 1 : 0;
            int s4 = (vm * (no - 1.5f * pe) >= 1.0f) ? 1 : 0;
            b13[o] = s1 + s2;
            b24[o] = s3 + s4;
        }

        int tmax = 0;
        #pragma unroll
        for (int o = 0; o < 4; ++o) {
            int d = b13[o] - b24[o];
            int tp = d < 0 ? -d : d;
            if (tp > tmax) tmax = tp;
        }

        uint32_t word = 0;
        #pragma unroll
        for (int o = 0; o < 4; ++o) {
            int d = b13[o] - b24[o];
            int tp = d < 0 ? -d : d;
            uint32_t nib = 0;
            if (tp == tmax) {
                if (d >= 1)
                    nib = (uint32_t)b13[o] | ((uint32_t)b24[o] << 2);
                else if (d <= -1)
                    nib = ((uint32_t)b24[o] << 4) | ((uint32_t)b13[o] << 6);
            }
            word |= nib << (8 * o);
        }
        g_border[((size_t)b * HH + (y0 + yy)) * WW + (x0 + tx)] = word;
    }
}

// ---------------------------------------------------------------------------
// Stage 2: depthwise 23x23 conv on 16 packed channels + spike combination.
// Block (32,8), tile 32x32. Each thread owns 4 vertical outputs; channel
// pairs (2*grp, 2*grp+1) share the same filter and ride in float2.
// ---------------------------------------------------------------------------
__global__ __launch_bounds__(256)
void stage2_kernel(const float* __restrict__ Wg, float* __restrict__ out)
{
    __shared__ float2 sh[54][56];
    __shared__ float wsh[529];

    const int b  = blockIdx.z;
    const int x0 = blockIdx.x * 32;
    const int y0 = blockIdx.y * 32;
    const int tx = threadIdx.x;   // 0..31 (lane-consecutive columns)
    const int ty = threadIdx.y;   // 0..7
    const int tid = ty * 32 + tx;
    const int yb = ty * 4;

    const uint32_t* __restrict__ bor = g_border + (size_t)b * HH * WW;

    float res0 = 0.f, res1 = 0.f, res2 = 0.f, res3 = 0.f;

    for (int grp = 0; grp < 8; ++grp) {
        __syncthreads();   // protect previous iteration's reads

        const int cA = grp * 2;
        const int shift = cA * 2;

        for (int i = tid; i < 529; i += 256) wsh[i] = Wg[cA * 529 + i];

        for (int i = tid; i < 54 * 54; i += 256) {
            int ry = i / 54, rx = i - ry * 54;
            int gy = y0 - 11 + ry, gx = x0 - 11 + rx;
            uint32_t v = 0;
            if (((unsigned)gy < HH) && ((unsigned)gx < WW)) v = bor[gy * WW + gx];
            sh[ry][rx] = make_float2((float)((v >> shift) & 3u),
                                     (float)((v >> (shift + 2)) & 3u));
        }
        __syncthreads();

        float2 a0 = {0.f,0.f}, a1 = {0.f,0.f}, a2 = {0.f,0.f}, a3 = {0.f,0.f};

        for (int dx = 0; dx < 23; ++dx) {
            const int c = tx + dx;
            float2 r0 = sh[yb + 0][c];
            float2 r1 = sh[yb + 1][c];
            float2 r2 = sh[yb + 2][c];
            #pragma unroll
            for (int dy = 0; dy < 23; ++dy) {
                float2 r3 = sh[yb + dy + 3][c];
                float w = wsh[dy * 23 + dx];
                a0.x += w * r0.x; a0.y += w * r0.y;
                a1.x += w * r1.x; a1.y += w * r1.y;
                a2.x += w * r2.x; a2.y += w * r2.y;
                a3.x += w * r3.x; a3.y += w * r3.y;
                r0 = r1; r1 = r2; r2 = r3;
            }
        }

        res0 += (a0.x >= 1.0f && a0.y < 1.0f) ? 1.0f : 0.0f;
        res1 += (a1.x >= 1.0f && a1.y < 1.0f) ? 1.0f : 0.0f;
        res2 += (a2.x >= 1.0f && a2.y < 1.0f) ? 1.0f : 0.0f;
        res3 += (a3.x >= 1.0f && a3.y < 1.0f) ? 1.0f : 0.0f;
    }

    float* o0 = out + ((size_t)b * HH + (y0 + yb)) * WW + x0 + tx;
    o0[0 * WW] = res0;
    o0[1 * WW] = res1;
    o0[2 * WW] = res2;
    o0[3 * WW] = res3;
}

// ---------------------------------------------------------------------------
extern "C" void kernel_launch(void* const* d_in, const int* in_sizes, int n_in,
                              void* d_out, int out_size)
{
    const float* inp = nullptr;
    const float* Wb  = nullptr;
    const float* Wg  = nullptr;
    for (int i = 0; i < n_in; ++i) {
        if (in_sizes[i] == NB * 2 * HH * WW) inp = (const float*)d_in[i];
        else if (in_sizes[i] == 8 * 121)     Wb  = (const float*)d_in[i];
        else if (in_sizes[i] == 16 * 529)    Wg  = (const float*)d_in[i];
    }

    dim3 grid1(WW / 32, HH / 32, NB);
    dim3 blk1(32, 16);
    stage1_kernel<<<grid1, blk1>>>(inp, Wb);

    dim3 grid2(WW / 32, HH / 32, NB);
    dim3 blk2(32, 8);
    stage2_kernel<<<grid2, blk2>>>(Wg, (float*)d_out);
}

// round 2
// speedup vs baseline: 1.1583x; 1.1583x over previous
#include <cuda_runtime.h>
#include <stdint.h>

#define HH 512
#define WW 512
#define NB 4

typedef unsigned long long ull;

// Packed border tensor: 16 channels x 2 bits per pixel (values in {0,1,2}).
__device__ uint32_t g_border[NB * HH * WW];

__device__ __forceinline__ ull ffma2(ull a, ull b, ull c) {
    ull d;
    asm("fma.rn.f32x2 %0, %1, %2, %3;" : "=l"(d) : "l"(a), "l"(b), "l"(c));
    return d;
}
__device__ __forceinline__ ull pack2(float x, float y) {
    ull d;
    asm("mov.b64 %0, {%1, %2};" : "=l"(d) : "f"(x), "f"(y));
    return d;
}
__device__ __forceinline__ float2 unpack2(ull v) {
    float2 r;
    asm("mov.b64 {%0, %1}, %2;" : "=f"(r.x), "=f"(r.y) : "l"(v));
    return r;
}

// ---------------------------------------------------------------------------
// Stage 1: 11x11 conv (1->8 ch) on both input planes + spike/WTA logic.
// Planes (in0,in1) interleaved as float2 -> every FFMA2 does pos+neg at once.
// Block (32,16), tile 32x32 (each thread owns rows ty and ty+16).
// ---------------------------------------------------------------------------
__global__ __launch_bounds__(512)
void stage1_kernel(const float* __restrict__ inp, const float* __restrict__ Wb)
{
    __shared__ ull s01[42][44];   // (in0,in1) packed  (14.8 KB)
    __shared__ ull wsh[968];      // duplicated weights (7.7 KB)

    const int b  = blockIdx.z;
    const int x0 = blockIdx.x * 32;
    const int y0 = blockIdx.y * 32;
    const int tx = threadIdx.x;      // 0..31
    const int ty = threadIdx.y;      // 0..15
    const int tid = ty * 32 + tx;

    for (int i = tid; i < 968; i += 512) {
        float w = Wb[i];
        wsh[i] = pack2(w, w);
    }

    const float* __restrict__ in0 = inp + ((size_t)b * 2 + 0) * HH * WW;
    const float* __restrict__ in1 = inp + ((size_t)b * 2 + 1) * HH * WW;

    for (int i = tid; i < 42 * 42; i += 512) {
        int ry = i / 42, rx = i - ry * 42;
        int gy = y0 - 5 + ry, gx = x0 - 5 + rx;
        bool ok = ((unsigned)gy < HH) && ((unsigned)gx < WW);
        float v0 = ok ? in0[gy * WW + gx] : 0.0f;
        float v1 = ok ? in1[gy * WW + gx] : 0.0f;
        s01[ry][rx] = pack2(v0, v1);
    }
    __syncthreads();

    ull acc0[8], acc1[8];            // .x = pos conv, .y = neg conv
    #pragma unroll
    for (int f = 0; f < 8; ++f) { acc0[f] = 0ull; acc1[f] = 0ull; }

    #pragma unroll 1
    for (int dy = 0; dy < 11; ++dy) {
        #pragma unroll
        for (int dx = 0; dx < 11; ++dx) {
            ull xa = s01[ty + dy][tx + dx];
            ull xb = s01[ty + 16 + dy][tx + dx];
            const int t = dy * 11 + dx;
            #pragma unroll
            for (int f = 0; f < 8; ++f) {
                ull w = wsh[f * 121 + t];
                acc0[f] = ffma2(w, xa, acc0[f]);
                acc1[f] = ffma2(w, xb, acc1[f]);
            }
        }
    }

    #pragma unroll
    for (int k = 0; k < 2; ++k) {
        const int yy = ty + k * 16;
        float2 ctr = unpack2(s01[yy + 5][tx + 5]);
        float vm = ctr.x + ctr.y;

        int b13[4], b24[4];
        #pragma unroll
        for (int o = 0; o < 4; ++o) {
            float2 e = unpack2(k == 0 ? acc0[2*o]   : acc1[2*o]);
            float2 d = unpack2(k == 0 ? acc0[2*o+1] : acc1[2*o+1]);
            float pe = e.x >= 1.0f ? 1.0f : 0.0f;
            float ne = e.y >= 1.0f ? 1.0f : 0.0f;
            float po = d.x >= 1.0f ? 1.0f : 0.0f;
            float no = d.y >= 1.0f ? 1.0f : 0.0f;
            int s1 = (vm * (pe - 1.5f * no) >= 1.0f) ? 1 : 0;
            int s2 = (vm * (ne - 1.5f * po) >= 1.0f) ? 1 : 0;
            int s3 = (vm * (po - 1.5f * ne) >= 1.0f) ? 1 : 0;
            int s4 = (vm * (no - 1.5f * pe) >= 1.0f) ? 1 : 0;
            b13[o] = s1 + s2;
            b24[o] = s3 + s4;
        }

        int tmax = 0;
        #pragma unroll
        for (int o = 0; o < 4; ++o) {
            int d = b13[o] - b24[o];
            int tp = d < 0 ? -d : d;
            if (tp > tmax) tmax = tp;
        }

        uint32_t word = 0;
        #pragma unroll
        for (int o = 0; o < 4; ++o) {
            int d = b13[o] - b24[o];
            int tp = d < 0 ? -d : d;
            uint32_t nib = 0;
            if (tp == tmax) {
                if (d >= 1)
                    nib = (uint32_t)b13[o] | ((uint32_t)b24[o] << 2);
                else if (d <= -1)
                    nib = ((uint32_t)b24[o] << 4) | ((uint32_t)b13[o] << 6);
            }
            word |= nib << (8 * o);
        }
        g_border[((size_t)b * HH + (y0 + yy)) * WW + (x0 + tx)] = word;
    }
}

// ---------------------------------------------------------------------------
// Stage 2: depthwise 23x23 conv on 16 packed channels + spike combination.
// Block (32,4), tile 32x32, 8 output rows per thread with an 8-register
// rolling window; channel pairs (2g, 2g+1) share a filter and ride in one
// packed FFMA2. Per dy-step: 1 LDS.64 + 1 broadcast LDS.64 for 8 FFMA2.
// ---------------------------------------------------------------------------
__global__ __launch_bounds__(128)
void stage2_kernel(const float* __restrict__ Wg, float* __restrict__ out)
{
    __shared__ ull sh[54][55];    // decoded (chanA, chanB) pairs (23.8 KB)
    __shared__ ull wsh[529];      // duplicated weights (4.2 KB)

    const int b  = blockIdx.z;
    const int x0 = blockIdx.x * 32;
    const int y0 = blockIdx.y * 32;
    const int tx = threadIdx.x;   // 0..31
    const int ty = threadIdx.y;   // 0..3
    const int tid = ty * 32 + tx;
    const int yb = ty * 8;

    const uint32_t* __restrict__ bor = g_border + (size_t)b * HH * WW;

    float res[8];
    #pragma unroll
    for (int o = 0; o < 8; ++o) res[o] = 0.0f;

    #pragma unroll 1
    for (int grp = 0; grp < 8; ++grp) {
        __syncthreads();   // protect previous iteration's reads

        const int shift = grp * 4;

        for (int i = tid; i < 529; i += 128) {
            float w = Wg[grp * 2 * 529 + i];
            wsh[i] = pack2(w, w);
        }

        for (int i = tid; i < 54 * 54; i += 128) {
            int ry = i / 54, rx = i - ry * 54;
            int gy = y0 - 11 + ry, gx = x0 - 11 + rx;
            uint32_t v = 0;
            if (((unsigned)gy < HH) && ((unsigned)gx < WW)) v = bor[gy * WW + gx];
            sh[ry][rx] = pack2((float)((v >> shift) & 3u),
                               (float)((v >> (shift + 2)) & 3u));
        }
        __syncthreads();

        ull a[8];
        #pragma unroll
        for (int o = 0; o < 8; ++o) a[o] = 0ull;

        #pragma unroll 1
        for (int dx = 0; dx < 23; ++dx) {
            const int c = tx + dx;
            ull r[8];
            #pragma unroll
            for (int o = 0; o < 8; ++o) r[o] = sh[yb + o][c];

            #pragma unroll
            for (int dy = 0; dy < 23; ++dy) {
                ull w = wsh[dy * 23 + dx];
                #pragma unroll
                for (int o = 0; o < 8; ++o) a[o] = ffma2(w, r[o], a[o]);
                if (dy < 22) {
                    #pragma unroll
                    for (int o = 0; o < 7; ++o) r[o] = r[o + 1];
                    r[7] = sh[yb + dy + 8][c];
                }
            }
        }

        #pragma unroll
        for (int o = 0; o < 8; ++o) {
            float2 v = unpack2(a[o]);
            res[o] += (v.x >= 1.0f && v.y < 1.0f) ? 1.0f : 0.0f;
        }
    }

    #pragma unroll
    for (int o = 0; o < 8; ++o)
        out[((size_t)b * HH + (y0 + yb + o)) * WW + x0 + tx] = res[o];
}

// ---------------------------------------------------------------------------
extern "C" void kernel_launch(void* const* d_in, const int* in_sizes, int n_in,
                              void* d_out, int out_size)
{
    const float* inp = nullptr;
    const float* Wb  = nullptr;
    const float* Wg  = nullptr;
    for (int i = 0; i < n_in; ++i) {
        if (in_sizes[i] == NB * 2 * HH * WW) inp = (const float*)d_in[i];
        else if (in_sizes[i] == 8 * 121)     Wb  = (const float*)d_in[i];
        else if (in_sizes[i] == 16 * 529)    Wg  = (const float*)d_in[i];
    }

    dim3 grid1(WW / 32, HH / 32, NB);
    dim3 blk1(32, 16);
    stage1_kernel<<<grid1, blk1>>>(inp, Wb);

    dim3 grid2(WW / 32, HH / 32, NB);
    dim3 blk2(32, 4);
    stage2_kernel<<<grid2, blk2>>>(Wg, (float*)d_out);
}

// round 3
// speedup vs baseline: 1.1824x; 1.0208x over previous
#include <cuda_runtime.h>
#include <stdint.h>

#define HH 512
#define WW 512
#define NB 4

typedef unsigned long long ull;

// Packed border tensor: 16 channels x 2 bits per pixel (values in {0,1,2}).
__device__ uint32_t g_border[NB * HH * WW];

__device__ __forceinline__ ull ffma2(ull a, ull b, ull c) {
    ull d;
    asm("fma.rn.f32x2 %0, %1, %2, %3;" : "=l"(d) : "l"(a), "l"(b), "l"(c));
    return d;
}
__device__ __forceinline__ ull pack2(float x, float y) {
    ull d;
    asm("mov.b64 %0, {%1, %2};" : "=l"(d) : "f"(x), "f"(y));
    return d;
}
__device__ __forceinline__ float2 unpack2(ull v) {
    float2 r;
    asm("mov.b64 {%0, %1}, %2;" : "=f"(r.x), "=f"(r.y) : "l"(v));
    return r;
}

// ---------------------------------------------------------------------------
// Zero the (0xAA-poisoned) output before REDG accumulation.
// ---------------------------------------------------------------------------
__global__ void zero_kernel(float4* __restrict__ out, int n4)
{
    int i = blockIdx.x * blockDim.x + threadIdx.x;
    if (i < n4) out[i] = make_float4(0.f, 0.f, 0.f, 0.f);
}

// ---------------------------------------------------------------------------
// Stage 1: 11x11 conv (1->8 ch) on both input planes + spike/WTA logic.
// Planes (in0,in1) interleaved as float2 -> every FFMA2 does pos+neg at once.
// Block (32,16), tile 32x32 (each thread owns rows ty and ty+16).
// ---------------------------------------------------------------------------
__global__ __launch_bounds__(512)
void stage1_kernel(const float* __restrict__ inp, const float* __restrict__ Wb)
{
    __shared__ ull s01[42][44];   // (in0,in1) packed  (14.8 KB)
    __shared__ ull wsh[968];      // duplicated weights (7.7 KB)

    const int b  = blockIdx.z;
    const int x0 = blockIdx.x * 32;
    const int y0 = blockIdx.y * 32;
    const int tx = threadIdx.x;      // 0..31
    const int ty = threadIdx.y;      // 0..15
    const int tid = ty * 32 + tx;

    for (int i = tid; i < 968; i += 512) {
        float w = Wb[i];
        wsh[i] = pack2(w, w);
    }

    const float* __restrict__ in0 = inp + ((size_t)b * 2 + 0) * HH * WW;
    const float* __restrict__ in1 = inp + ((size_t)b * 2 + 1) * HH * WW;

    for (int i = tid; i < 42 * 42; i += 512) {
        int ry = i / 42, rx = i - ry * 42;
        int gy = y0 - 5 + ry, gx = x0 - 5 + rx;
        bool ok = ((unsigned)gy < HH) && ((unsigned)gx < WW);
        float v0 = ok ? in0[gy * WW + gx] : 0.0f;
        float v1 = ok ? in1[gy * WW + gx] : 0.0f;
        s01[ry][rx] = pack2(v0, v1);
    }
    __syncthreads();

    ull acc0[8], acc1[8];            // .x = pos conv, .y = neg conv
    #pragma unroll
    for (int f = 0; f < 8; ++f) { acc0[f] = 0ull; acc1[f] = 0ull; }

    #pragma unroll 1
    for (int dy = 0; dy < 11; ++dy) {
        #pragma unroll
        for (int dx = 0; dx < 11; ++dx) {
            ull xa = s01[ty + dy][tx + dx];
            ull xb = s01[ty + 16 + dy][tx + dx];
            const int t = dy * 11 + dx;
            #pragma unroll
            for (int f = 0; f < 8; ++f) {
                ull w = wsh[f * 121 + t];
                acc0[f] = ffma2(w, xa, acc0[f]);
                acc1[f] = ffma2(w, xb, acc1[f]);
            }
        }
    }

    #pragma unroll
    for (int k = 0; k < 2; ++k) {
        const int yy = ty + k * 16;
        float2 ctr = unpack2(s01[yy + 5][tx + 5]);
        float vm = ctr.x + ctr.y;

        int b13[4], b24[4];
        #pragma unroll
        for (int o = 0; o < 4; ++o) {
            float2 e = unpack2(k == 0 ? acc0[2*o]   : acc1[2*o]);
            float2 d = unpack2(k == 0 ? acc0[2*o+1] : acc1[2*o+1]);
            float pe = e.x >= 1.0f ? 1.0f : 0.0f;
            float ne = e.y >= 1.0f ? 1.0f : 0.0f;
            float po = d.x >= 1.0f ? 1.0f : 0.0f;
            float no = d.y >= 1.0f ? 1.0f : 0.0f;
            int s1 = (vm * (pe - 1.5f * no) >= 1.0f) ? 1 : 0;
            int s2 = (vm * (ne - 1.5f * po) >= 1.0f) ? 1 : 0;
            int s3 = (vm * (po - 1.5f * ne) >= 1.0f) ? 1 : 0;
            int s4 = (vm * (no - 1.5f * pe) >= 1.0f) ? 1 : 0;
            b13[o] = s1 + s2;
            b24[o] = s3 + s4;
        }

        int tmax = 0;
        #pragma unroll
        for (int o = 0; o < 4; ++o) {
            int d = b13[o] - b24[o];
            int tp = d < 0 ? -d : d;
            if (tp > tmax) tmax = tp;
        }

        uint32_t word = 0;
        #pragma unroll
        for (int o = 0; o < 4; ++o) {
            int d = b13[o] - b24[o];
            int tp = d < 0 ? -d : d;
            uint32_t nib = 0;
            if (tp == tmax) {
                if (d >= 1)
                    nib = (uint32_t)b13[o] | ((uint32_t)b24[o] << 2);
                else if (d <= -1)
                    nib = ((uint32_t)b24[o] << 4) | ((uint32_t)b13[o] << 6);
            }
            word |= nib << (8 * o);
        }
        g_border[((size_t)b * HH + (y0 + yy)) * WW + (x0 + tx)] = word;
    }
}

// ---------------------------------------------------------------------------
// Stage 2: depthwise 23x23 conv + spike combination. ONE (tile, group) per
// block: no group loop, no repeated barriers -> fills of incoming blocks
// overlap computes of resident blocks. Results combine via predicated
// atomicAdd (REDG.ADD.F32) since group spikes are additively independent.
// Block (32,4), tile 32x32, 8 output rows/thread, channel pair in FFMA2.
// ---------------------------------------------------------------------------
__global__ __launch_bounds__(128)
void stage2_kernel(const float* __restrict__ Wg, float* __restrict__ out)
{
    __shared__ ull sh[54][55];    // decoded (chanA, chanB) pairs (23.8 KB)
    __shared__ ull wsh[529];      // duplicated weights (4.2 KB)

    const int zz  = blockIdx.z;          // 0..31 = b*8 + grp
    const int b   = zz >> 3;
    const int grp = zz & 7;
    const int x0 = blockIdx.x * 32;
    const int y0 = blockIdx.y * 32;
    const int tx = threadIdx.x;   // 0..31
    const int ty = threadIdx.y;   // 0..3
    const int tid = ty * 32 + tx;
    const int yb = ty * 8;

    const uint32_t* __restrict__ bor = g_border + (size_t)b * HH * WW;
    const int shift = grp * 4;

    for (int i = tid; i < 529; i += 128) {
        float w = Wg[grp * 2 * 529 + i];
        wsh[i] = pack2(w, w);
    }

    for (int i = tid; i < 54 * 54; i += 128) {
        int ry = i / 54, rx = i - ry * 54;
        int gy = y0 - 11 + ry, gx = x0 - 11 + rx;
        uint32_t v = 0;
        if (((unsigned)gy < HH) && ((unsigned)gx < WW)) v = bor[gy * WW + gx];
        sh[ry][rx] = pack2((float)((v >> shift) & 3u),
                           (float)((v >> (shift + 2)) & 3u));
    }
    __syncthreads();

    ull a[8];
    #pragma unroll
    for (int o = 0; o < 8; ++o) a[o] = 0ull;

    #pragma unroll 1
    for (int dx = 0; dx < 23; ++dx) {
        const int c = tx + dx;
        ull r[8];
        #pragma unroll
        for (int o = 0; o < 8; ++o) r[o] = sh[yb + o][c];

        #pragma unroll
        for (int dy = 0; dy < 23; ++dy) {
            ull w = wsh[dy * 23 + dx];
            #pragma unroll
            for (int o = 0; o < 8; ++o) a[o] = ffma2(w, r[o], a[o]);
            if (dy < 22) {
                #pragma unroll
                for (int o = 0; o < 7; ++o) r[o] = r[o + 1];
                r[7] = sh[yb + dy + 8][c];
            }
        }
    }

    #pragma unroll
    for (int o = 0; o < 8; ++o) {
        float2 v = unpack2(a[o]);
        if (v.x >= 1.0f && v.y < 1.0f)
            atomicAdd(&out[((size_t)b * HH + (y0 + yb + o)) * WW + x0 + tx], 1.0f);
    }
}

// ---------------------------------------------------------------------------
extern "C" void kernel_launch(void* const* d_in, const int* in_sizes, int n_in,
                              void* d_out, int out_size)
{
    const float* inp = nullptr;
    const float* Wb  = nullptr;
    const float* Wg  = nullptr;
    for (int i = 0; i < n_in; ++i) {
        if (in_sizes[i] == NB * 2 * HH * WW) inp = (const float*)d_in[i];
        else if (in_sizes[i] == 8 * 121)     Wb  = (const float*)d_in[i];
        else if (in_sizes[i] == 16 * 529)    Wg  = (const float*)d_in[i];
    }

    // Zero the poisoned output (stage2 accumulates via atomics).
    int n4 = out_size / 4;
    zero_kernel<<<(n4 + 255) / 256, 256>>>((float4*)d_out, n4);

    dim3 grid1(WW / 32, HH / 32, NB);
    dim3 blk1(32, 16);
    stage1_kernel<<<grid1, blk1>>>(inp, Wb);

    dim3 grid2(WW / 32, HH / 32, NB * 8);   // one (tile, group) per block
    dim3 blk2(32, 4);
    stage2_kernel<<<grid2, blk2>>>(Wg, (float*)d_out);
}

// round 4
// speedup vs baseline: 1.2070x; 1.0208x over previous
#include <cuda_runtime.h>
#include <stdint.h>

#define HH 512
#define WW 512
#define NB 4

typedef unsigned long long ull;

// Packed border tensor: 16 channels x 2 bits per pixel (values in {0,1,2}).
__device__ uint32_t g_border[NB * HH * WW];

__device__ __forceinline__ ull ffma2(ull a, ull b, ull c) {
    ull d;
    asm("fma.rn.f32x2 %0, %1, %2, %3;" : "=l"(d) : "l"(a), "l"(b), "l"(c));
    return d;
}
__device__ __forceinline__ ull pack2(float x, float y) {
    ull d;
    asm("mov.b64 %0, {%1, %2};" : "=l"(d) : "f"(x), "f"(y));
    return d;
}
__device__ __forceinline__ float2 unpack2(ull v) {
    float2 r;
    asm("mov.b64 {%0, %1}, %2;" : "=f"(r.x), "=f"(r.y) : "l"(v));
    return r;
}

// ---------------------------------------------------------------------------
// Stage 1: 11x11 conv (1->8 ch) on both input planes + spike/WTA logic.
// Planes (in0,in1) ride in one FFMA2. Duplicated weights stored [tap][filter]
// so each tap's 8 weights come from 4 broadcast LDS.128 -> LSU 6cyc < fma 8cyc.
// Block (32,16), tile 32x32 (each thread owns rows ty and ty+16).
// Also zeroes d_out (stage2 accumulates via atomics).
// ---------------------------------------------------------------------------
__global__ __launch_bounds__(512)
void stage1_kernel(const float* __restrict__ inp, const float* __restrict__ Wb,
                   float* __restrict__ out)
{
    __shared__ ull s01[42][44];                  // (in0,in1) packed (14.8 KB)
    __shared__ __align__(16) ull dsh[121 * 8];   // dup weights [t][f] (7.7 KB)

    const int b  = blockIdx.z;
    const int x0 = blockIdx.x * 32;
    const int y0 = blockIdx.y * 32;
    const int tx = threadIdx.x;      // 0..31
    const int ty = threadIdx.y;      // 0..15
    const int tid = ty * 32 + tx;

    for (int i = tid; i < 968; i += 512) {
        int t = i >> 3, f = i & 7;
        float w = Wb[f * 121 + t];
        dsh[i] = pack2(w, w);
    }

    const float* __restrict__ in0 = inp + ((size_t)b * 2 + 0) * HH * WW;
    const float* __restrict__ in1 = inp + ((size_t)b * 2 + 1) * HH * WW;

    for (int i = tid; i < 42 * 42; i += 512) {
        int ry = i / 42, rx = i - ry * 42;
        int gy = y0 - 5 + ry, gx = x0 - 5 + rx;
        bool ok = ((unsigned)gy < HH) && ((unsigned)gx < WW);
        float v0 = ok ? in0[gy * WW + gx] : 0.0f;
        float v1 = ok ? in1[gy * WW + gx] : 0.0f;
        s01[ry][rx] = pack2(v0, v1);
    }
    __syncthreads();

    ull acc0[8], acc1[8];            // .x = pos conv, .y = neg conv
    #pragma unroll
    for (int f = 0; f < 8; ++f) { acc0[f] = 0ull; acc1[f] = 0ull; }

    #pragma unroll 1
    for (int dy = 0; dy < 11; ++dy) {
        #pragma unroll
        for (int dx = 0; dx < 11; ++dx) {
            ull xa = s01[ty + dy][tx + dx];
            ull xb = s01[ty + 16 + dy][tx + dx];
            const int t = dy * 11 + dx;
            const ulonglong2* wp = (const ulonglong2*)&dsh[t * 8];
            #pragma unroll
            for (int fp = 0; fp < 4; ++fp) {
                ulonglong2 w2 = wp[fp];
                acc0[2*fp]   = ffma2(w2.x, xa, acc0[2*fp]);
                acc1[2*fp]   = ffma2(w2.x, xb, acc1[2*fp]);
                acc0[2*fp+1] = ffma2(w2.y, xa, acc0[2*fp+1]);
                acc1[2*fp+1] = ffma2(w2.y, xb, acc1[2*fp+1]);
            }
        }
    }

    #pragma unroll
    for (int k = 0; k < 2; ++k) {
        const int yy = ty + k * 16;
        float2 ctr = unpack2(s01[yy + 5][tx + 5]);
        float vm = ctr.x + ctr.y;

        int b13[4], b24[4];
        #pragma unroll
        for (int o = 0; o < 4; ++o) {
            float2 e = unpack2(k == 0 ? acc0[2*o]   : acc1[2*o]);
            float2 d = unpack2(k == 0 ? acc0[2*o+1] : acc1[2*o+1]);
            float pe = e.x >= 1.0f ? 1.0f : 0.0f;
            float ne = e.y >= 1.0f ? 1.0f : 0.0f;
            float po = d.x >= 1.0f ? 1.0f : 0.0f;
            float no = d.y >= 1.0f ? 1.0f : 0.0f;
            int s1 = (vm * (pe - 1.5f * no) >= 1.0f) ? 1 : 0;
            int s2 = (vm * (ne - 1.5f * po) >= 1.0f) ? 1 : 0;
            int s3 = (vm * (po - 1.5f * ne) >= 1.0f) ? 1 : 0;
            int s4 = (vm * (no - 1.5f * pe) >= 1.0f) ? 1 : 0;
            b13[o] = s1 + s2;
            b24[o] = s3 + s4;
        }

        int tmax = 0;
        #pragma unroll
        for (int o = 0; o < 4; ++o) {
            int d = b13[o] - b24[o];
            int tp = d < 0 ? -d : d;
            if (tp > tmax) tmax = tp;
        }

        uint32_t word = 0;
        #pragma unroll
        for (int o = 0; o < 4; ++o) {
            int d = b13[o] - b24[o];
            int tp = d < 0 ? -d : d;
            uint32_t nib = 0;
            if (tp == tmax) {
                if (d >= 1)
                    nib = (uint32_t)b13[o] | ((uint32_t)b24[o] << 2);
                else if (d <= -1)
                    nib = ((uint32_t)b24[o] << 4) | ((uint32_t)b13[o] << 6);
            }
            word |= nib << (8 * o);
        }
        const size_t pix = ((size_t)b * HH + (y0 + yy)) * WW + (x0 + tx);
        g_border[pix] = word;
        out[pix] = 0.0f;   // zero-init for stage2's atomic accumulation
    }
}

// ---------------------------------------------------------------------------
// Stage 2: depthwise 23x23 conv + spike combination. ONE (tile, group) per
// block; results combine via predicated atomicAdd. Block (32,2), tile 32x32,
// 16 output rows/thread with a 16-register rolling window; channel pair in
// one FFMA2. Per dy-step: 16 FFMA2 vs 1 data LDS.64 + 1 broadcast LDS.64.
// ---------------------------------------------------------------------------
__global__ __launch_bounds__(64)
void stage2_kernel(const float* __restrict__ Wg, float* __restrict__ out)
{
    __shared__ ull sh[54][55];    // decoded (chanA, chanB) pairs (23.8 KB)
    __shared__ ull wsh[529];      // duplicated weights (4.2 KB)

    const int zz  = blockIdx.z;          // 0..31 = b*8 + grp
    const int b   = zz >> 3;
    const int grp = zz & 7;
    const int x0 = blockIdx.x * 32;
    const int y0 = blockIdx.y * 32;
    const int tx = threadIdx.x;   // 0..31
    const int ty = threadIdx.y;   // 0..1
    const int tid = ty * 32 + tx;
    const int yb = ty * 16;

    const uint32_t* __restrict__ bor = g_border + (size_t)b * HH * WW;
    const int shift = grp * 4;

    for (int i = tid; i < 529; i += 64) {
        float w = Wg[grp * 2 * 529 + i];
        wsh[i] = pack2(w, w);
    }

    for (int i = tid; i < 54 * 54; i += 64) {
        int ry = i / 54, rx = i - ry * 54;
        int gy = y0 - 11 + ry, gx = x0 - 11 + rx;
        uint32_t v = 0;
        if (((unsigned)gy < HH) && ((unsigned)gx < WW)) v = bor[gy * WW + gx];
        sh[ry][rx] = pack2((float)((v >> shift) & 3u),
                           (float)((v >> (shift + 2)) & 3u));
    }
    __syncthreads();

    ull a[16];
    #pragma unroll
    for (int o = 0; o < 16; ++o) a[o] = 0ull;

    #pragma unroll 1
    for (int dx = 0; dx < 23; ++dx) {
        const int c = tx + dx;
        ull r[16];
        #pragma unroll
        for (int o = 0; o < 16; ++o) r[o] = sh[yb + o][c];

        #pragma unroll
        for (int dy = 0; dy < 23; ++dy) {
            ull w = wsh[dy * 23 + dx];
            #pragma unroll
            for (int o = 0; o < 16; ++o) a[o] = ffma2(w, r[o], a[o]);
            if (dy < 22) {
                #pragma unroll
                for (int o = 0; o < 15; ++o) r[o] = r[o + 1];
                r[15] = sh[yb + dy + 16][c];
            }
        }
    }

    #pragma unroll
    for (int o = 0; o < 16; ++o) {
        float2 v = unpack2(a[o]);
        if (v.x >= 1.0f && v.y < 1.0f)
            atomicAdd(&out[((size_t)b * HH + (y0 + yb + o)) * WW + x0 + tx], 1.0f);
    }
}

// ---------------------------------------------------------------------------
extern "C" void kernel_launch(void* const* d_in, const int* in_sizes, int n_in,
                              void* d_out, int out_size)
{
    const float* inp = nullptr;
    const float* Wb  = nullptr;
    const float* Wg  = nullptr;
    for (int i = 0; i < n_in; ++i) {
        if (in_sizes[i] == NB * 2 * HH * WW) inp = (const float*)d_in[i];
        else if (in_sizes[i] == 8 * 121)     Wb  = (const float*)d_in[i];
        else if (in_sizes[i] == 16 * 529)    Wg  = (const float*)d_in[i];
    }

    dim3 grid1(WW / 32, HH / 32, NB);
    dim3 blk1(32, 16);
    stage1_kernel<<<grid1, blk1>>>(inp, Wb, (float*)d_out);

    dim3 grid2(WW / 32, HH / 32, NB * 8);   // one (tile, group) per block
    dim3 blk2(32, 2);
    stage2_kernel<<<grid2, blk2>>>(Wg, (float*)d_out);
}